// round 9
// baseline (speedup 1.0000x reference)
#include <cuda_runtime.h>
#include <cuda_fp16.h>

// SpectrumEncoding: out[b,d] = sum_n pe[ceil(loc[b,n]*10), d] * inten[b,n]
// B=1024, N=500, D=512.
//
// R8 finding: gather (35.5us) is latency/queue-bound (issue 31%, L2 ~64%);
// suspect LDS->LDG serialization capping the in-flight LDG window.
// Convert (13.7us) is at the HBM wall. R9: batch 5 LDS then 5 LDG.128 per
// block (explicit 5-deep window), fuse the reduce pass into convert(zero) +
// gather(atomicAdd, 2 contenders/addr).

#define N_PEAKS    500
#define HALF_PEAKS 250
#define D_MODEL    512
#define RESO       10.0f
#define TABLE_ROWS 30001
#define ROW_U4     (D_MODEL / 8) // 64 uint4 (8 halves) per fp16 row

// fp16 copy of pe, rebuilt each call (30.7 MB).
__device__ uint4 g_peh[TABLE_ROWS * ROW_U4];

// ---------------------------------------------------------------------------
// Pass 1: f32 -> f16 convert (8-deep unroll, MLP=8) + zero d_out.
// Grid is exactly 2048*256 = 524288 threads = out element count.
// ---------------------------------------------------------------------------
__global__ void convert_pe_kernel(const float4* __restrict__ pe4,
                                  float*        __restrict__ out)
{
    uint2* __restrict__ dst = reinterpret_cast<uint2*>(g_peh);
    const int total  = TABLE_ROWS * (D_MODEL / 4);   // 3,840,128 uint2
    const int stride = gridDim.x * blockDim.x;       // 524,288
    const int i0     = blockIdx.x * blockDim.x + threadIdx.x;

    out[i0] = 0.0f;                                  // one float per thread

    #pragma unroll 8
    for (int j = 0; j < 8; ++j) {
        const int k = i0 + j * stride;
        if (k < total) {
            float4 v = pe4[k];
            __half2 h0 = __floats2half2_rn(v.x, v.y);
            __half2 h1 = __floats2half2_rn(v.z, v.w);
            uint2 p;
            p.x = *reinterpret_cast<unsigned*>(&h0);
            p.y = *reinterpret_cast<unsigned*>(&h1);
            dst[k] = p;
        }
    }
}

// ---------------------------------------------------------------------------
// Pass 2: gather + weighted reduce.
// CTA = (batch row, peak half): 250 peaks. 128 threads = 2 groups of 64;
// group g handles peak 2*it+g. Per 5-block: 5 LDS, then 5 independent
// LDG.128, then fp16 HFMA2 chains (len 5), flushed to f32. Epilogue:
// smem-combine the 2 groups, then 8 atomicAdds into out.
// ---------------------------------------------------------------------------
__global__ __launch_bounds__(128)
void SpectrumEncoding_kernel(const float*  __restrict__ loc,
                             const float*  __restrict__ inten,
                             float*        __restrict__ out)
{
    __shared__ float2 s_iw[HALF_PEAKS];  // .x = (idx*ROW_U4) bits, .y = half2(w,w) bits
    __shared__ float4 s_red[128];        // group-1 accumulators (2 KB)

    const int cta  = blockIdx.x;         // 0..2047
    const int b    = cta >> 1;
    const int nbeg = (cta & 1) * HALF_PEAKS;
    const int t    = threadIdx.x;
    const int g    = t >> 6;             // thread-group 0/1 (2 warps each)
    const int t64  = t & 63;

    const float* lrow = loc   + (long long)b * N_PEAKS + nbeg;
    const float* irow = inten + (long long)b * N_PEAKS + nbeg;

    for (int n = t; n < HALF_PEAKS; n += 128) {
        int idx = (int)ceilf(lrow[n] * RESO);
        __half2 w2 = __half2half2(__float2half(irow[n]));
        s_iw[n] = make_float2(__int_as_float(idx * ROW_U4),
                              __uint_as_float(*reinterpret_cast<unsigned*>(&w2)));
    }
    __syncthreads();

    float4 a0 = make_float4(0.f, 0.f, 0.f, 0.f);
    float4 a1 = make_float4(0.f, 0.f, 0.f, 0.f);

    for (int blk = 0; blk < 25; ++blk) {
        // Stage 1: all 5 index/weight pairs (LDS, warp-uniform broadcast).
        float2 iw[5];
        #pragma unroll
        for (int j = 0; j < 5; ++j)
            iw[j] = s_iw[(blk * 5 + j) * 2 + g];

        // Stage 2: 5 independent LDG.128 back-to-back.
        uint4 v[5];
        #pragma unroll
        for (int j = 0; j < 5; ++j)
            v[j] = __ldg(&g_peh[__float_as_int(iw[j].x) + t64]);

        // Stage 3: fp16 accumulate (chain length 5), then flush to f32.
        __half2 h0 = __half2half2(__ushort_as_half(0));
        __half2 h1 = h0, h2 = h0, h3 = h0;
        #pragma unroll
        for (int j = 0; j < 5; ++j) {
            const unsigned wb = __float_as_uint(iw[j].y);
            const __half2  w2 = *reinterpret_cast<const __half2*>(&wb);
            h0 = __hfma2(*reinterpret_cast<const __half2*>(&v[j].x), w2, h0);
            h1 = __hfma2(*reinterpret_cast<const __half2*>(&v[j].y), w2, h1);
            h2 = __hfma2(*reinterpret_cast<const __half2*>(&v[j].z), w2, h2);
            h3 = __hfma2(*reinterpret_cast<const __half2*>(&v[j].w), w2, h3);
        }

        const float2 f0 = __half22float2(h0);
        const float2 f1 = __half22float2(h1);
        const float2 f2 = __half22float2(h2);
        const float2 f3 = __half22float2(h3);
        a0.x += f0.x; a0.y += f0.y; a0.z += f1.x; a0.w += f1.y;
        a1.x += f2.x; a1.y += f2.y; a1.z += f3.x; a1.w += f3.y;
    }

    // Combine the two peak-groups, then atomically add into out
    // (exactly 2 contenders per address: the two peak-half CTAs).
    if (g == 1) {
        s_red[t64]      = a0;
        s_red[64 + t64] = a1;
    }
    __syncthreads();
    if (g == 0) {
        const float4 b0 = s_red[t64];
        const float4 b1 = s_red[64 + t64];
        a0.x += b0.x; a0.y += b0.y; a0.z += b0.z; a0.w += b0.w;
        a1.x += b1.x; a1.y += b1.y; a1.z += b1.z; a1.w += b1.w;
        float* orow = out + (long long)b * D_MODEL + 8 * t64;
        atomicAdd(orow + 0, a0.x);
        atomicAdd(orow + 1, a0.y);
        atomicAdd(orow + 2, a0.z);
        atomicAdd(orow + 3, a0.w);
        atomicAdd(orow + 4, a1.x);
        atomicAdd(orow + 5, a1.y);
        atomicAdd(orow + 6, a1.z);
        atomicAdd(orow + 7, a1.w);
    }
}

extern "C" void kernel_launch(void* const* d_in, const int* in_sizes, int n_in,
                              void* d_out, int out_size)
{
    const float*  loc   = (const float*)d_in[0];   // [B, 500]
    const float*  inten = (const float*)d_in[1];   // [B, 500]
    const float4* pe4   = (const float4*)d_in[2];  // [30001, 512] f32
    float*        out   = (float*)d_out;           // [B, 512] f32

    const int B = in_sizes[0] / N_PEAKS;           // 1024

    convert_pe_kernel<<<2048, 256>>>(pe4, out);    // 524288 threads == out elems
    SpectrumEncoding_kernel<<<B * 2, 128>>>(loc, inten, out);
}